// round 5
// baseline (speedup 1.0000x reference)
#include <cuda_runtime.h>
#include <cuda_bf16.h>
#include <math.h>

#define N_NODES 25000
#define N_EDGES 400000
#define HID 64
#define EMB 8
#define N_GRAPHS 16
#define N_CLASSES 10
#define KDIM 512   /* EMB*HID */

// ---------------- scratch (device globals; no allocation allowed) ----------
__device__ float g_B[(size_t)N_NODES * KDIM];     // 51.2 MB  B[n, i*64+j]
__device__ float g_hA[N_NODES * HID];
__device__ float g_hB[N_NODES * HID];
__device__ float g_R[N_NODES * HID];              // relu(agg)
__device__ float g_D[(size_t)N_EDGES * EMB];      // directions in ORIGINAL edge order
__device__ int2  g_se[N_EDGES];                   // CSR-ordered {src, edge_id}
__device__ int   g_rowptr[N_NODES + 1];
__device__ int   g_cnt[N_NODES];
__device__ int   g_cur[N_NODES];
__device__ float g_sums[HID];
__device__ float g_sumsq[HID];
__device__ float g_pooled[N_GRAPHS * HID];
__device__ int   g_done;

// ---------------- tf32 helpers ---------------------------------------------
__device__ __forceinline__ unsigned tf32cvt(float x) {
    unsigned r;
    asm("cvt.rna.tf32.f32 %0, %1;" : "=r"(r) : "f"(x));
    return r;
}
__device__ __forceinline__ void mma_tf32(float* c,
                                         unsigned a0, unsigned a1, unsigned a2, unsigned a3,
                                         unsigned b0, unsigned b1) {
    asm volatile(
        "mma.sync.aligned.m16n8k8.row.col.f32.tf32.tf32.f32 "
        "{%0,%1,%2,%3}, {%4,%5,%6,%7}, {%8,%9}, {%0,%1,%2,%3};"
        : "+f"(c[0]), "+f"(c[1]), "+f"(c[2]), "+f"(c[3])
        : "r"(a0), "r"(a1), "r"(a2), "r"(a3), "r"(b0), "r"(b1));
}

// ---------------- CSR build ------------------------------------------------
__global__ void k_zero_cc() {
    int i = blockIdx.x * blockDim.x + threadIdx.x;
    if (i < N_NODES) { g_cnt[i] = 0; g_cur[i] = 0; }
}

// histogram of dst + per-edge normalized direction (coalesced write, edge order)
__global__ void k_hist_dir(const int* __restrict__ src, const int* __restrict__ dst,
                           const float* __restrict__ c) {
    int e = blockIdx.x * blockDim.x + threadIdx.x;
    if (e >= N_EDGES) return;
    int s = src[e], t = dst[e];
    atomicAdd(&g_cnt[t], 1);
    float4 s0 = __ldg((const float4*)&c[s * EMB]);
    float4 s1 = __ldg((const float4*)&c[s * EMB + 4]);
    float4 t0 = __ldg((const float4*)&c[t * EMB]);
    float4 t1 = __ldg((const float4*)&c[t * EMB + 4]);
    float4 d0 = make_float4(s0.x - t0.x, s0.y - t0.y, s0.z - t0.z, s0.w - t0.w);
    float4 d1 = make_float4(s1.x - t1.x, s1.y - t1.y, s1.z - t1.z, s1.w - t1.w);
    float nn = d0.x * d0.x + d0.y * d0.y + d0.z * d0.z + d0.w * d0.w
             + d1.x * d1.x + d1.y * d1.y + d1.z * d1.z + d1.w * d1.w;
    float sc = 1.0f / fmaxf(sqrtf(nn), 1e-12f);
    d0.x *= sc; d0.y *= sc; d0.z *= sc; d0.w *= sc;
    d1.x *= sc; d1.y *= sc; d1.z *= sc; d1.w *= sc;
    *(float4*)&g_D[(size_t)e * EMB]     = d0;
    *(float4*)&g_D[(size_t)e * EMB + 4] = d1;
}

// single-block scan: 1024 threads x 25 contiguous counts each (25600 >= 25001)
__global__ void k_scan() {
    const int PER = 25;
    __shared__ int wsum[32];
    int tid = threadIdx.x, lane = tid & 31, wid = tid >> 5;
    int base = tid * PER;
    int v[PER];
    int s = 0;
    #pragma unroll
    for (int j = 0; j < PER; j++) {
        int i = base + j;
        int cv = (i < N_NODES) ? g_cnt[i] : 0;
        v[j] = s;
        s += cv;
    }
    int x = s;
    #pragma unroll
    for (int o = 1; o < 32; o <<= 1) {
        int t = __shfl_up_sync(0xffffffffu, x, o);
        if (lane >= o) x += t;
    }
    if (lane == 31) wsum[wid] = x;
    __syncthreads();
    if (wid == 0) {
        int w = wsum[lane];
        #pragma unroll
        for (int o = 1; o < 32; o <<= 1) {
            int t = __shfl_up_sync(0xffffffffu, w, o);
            if (lane >= o) w += t;
        }
        wsum[lane] = w;
    }
    __syncthreads();
    int off = x - s + (wid > 0 ? wsum[wid - 1] : 0);
    #pragma unroll
    for (int j = 0; j < PER; j++) {
        int i = base + j;
        if (i <= N_NODES) g_rowptr[i] = off + v[j];
    }
}

// scatter edge -> CSR slot; only 8 bytes scattered per edge
__global__ void k_scatter(const int* __restrict__ src, const int* __restrict__ dst) {
    int e = blockIdx.x * blockDim.x + threadIdx.x;
    if (e >= N_EDGES) return;
    int s = src[e], t = dst[e];
    int p = g_rowptr[t] + atomicAdd(&g_cur[t], 1);
    g_se[p] = make_int2(s, e);
}

// ---------------- edge aggregation: B[n,i,j] = sum_{e:dst=n} d_i * h[src,j] ----
// One warp per dst node. The warp cooperatively preloads up to 32 CSR entries
// with ONE coalesced LDG.64, then broadcasts via shfl: all per-edge loads are
// address-independent -> deep MLP, LSU-throughput bound instead of latency.
__global__ void k_edge_agg(const float* __restrict__ feat, int hsel) {
    if (blockIdx.x == 0) {   // piggyback: zero per-layer reduction buffers
        int t = threadIdx.x;
        if (t < HID) { g_sums[t] = 0.f; g_sumsq[t] = 0.f; }
        if (t == 0) g_done = 0;
        for (int i = t; i < N_GRAPHS * HID; i += blockDim.x) g_pooled[i] = 0.f;
    }
    const float* __restrict__ h = (hsel == 0) ? feat : ((hsel == 1) ? g_hA : g_hB);
    int w = (blockIdx.x * blockDim.x + threadIdx.x) >> 5;
    int lane = threadIdx.x & 31;
    if (w >= N_NODES) return;
    int e0 = g_rowptr[w], e1 = g_rowptr[w + 1];
    float a0[EMB], a1[EMB];
    #pragma unroll
    for (int i = 0; i < EMB; i++) { a0[i] = 0.f; a1[i] = 0.f; }

    for (int base = e0; base < e1; base += 32) {
        int n = e1 - base; if (n > 32) n = 32;
        int2 se = make_int2(0, 0);
        if (base + lane < e1) se = __ldg(&g_se[base + lane]);
        #pragma unroll 4
        for (int j = 0; j < n; j++) {
            int sx = __shfl_sync(0xffffffffu, se.x, j);
            int ey = __shfl_sync(0xffffffffu, se.y, j);
            float4 d0 = __ldg((const float4*)&g_D[(size_t)ey * EMB]);
            float4 d1 = __ldg((const float4*)&g_D[(size_t)ey * EMB + 4]);
            float h0 = __ldg(&h[sx * HID + lane]);
            float h1 = __ldg(&h[sx * HID + 32 + lane]);
            a0[0] += d0.x * h0;  a1[0] += d0.x * h1;
            a0[1] += d0.y * h0;  a1[1] += d0.y * h1;
            a0[2] += d0.z * h0;  a1[2] += d0.z * h1;
            a0[3] += d0.w * h0;  a1[3] += d0.w * h1;
            a0[4] += d1.x * h0;  a1[4] += d1.x * h1;
            a0[5] += d1.y * h0;  a1[5] += d1.y * h1;
            a0[6] += d1.z * h0;  a1[6] += d1.z * h1;
            a0[7] += d1.w * h0;  a1[7] += d1.w * h1;
        }
    }
    float* out = &g_B[(size_t)w * KDIM];
    #pragma unroll
    for (int i = 0; i < EMB; i++) {
        out[i * HID + lane] = a0[i];
        out[i * HID + 32 + lane] = a1[i];
    }
}

// -------- tf32 tensor-core GEMM: R = relu(B[25000,512] @ W[512,64]) + BN stats --
#define BM 64
#define BK 32
__global__ void k_gemm_relu(const float* __restrict__ W) {
    __shared__ unsigned As[BM][36];   // stride 36: A-frag loads conflict-free
    __shared__ unsigned Bs[BK][72];   // stride 72: B-frag loads conflict-free
    int tid = threadIdx.x;            // 128
    int lane = tid & 31, w = tid >> 5;
    int g = lane >> 2, tig = lane & 3;
    int rowBase = blockIdx.x * BM;
    int wrow = w * 16;
    float acc[8][4];
    #pragma unroll
    for (int nt = 0; nt < 8; nt++)
        #pragma unroll
        for (int j = 0; j < 4; j++) acc[nt][j] = 0.f;

    for (int kb = 0; kb < KDIM; kb += BK) {
        #pragma unroll
        for (int it = 0; it < 4; it++) {
            int f = tid + 128 * it;
            int r = f >> 3, q = f & 7;
            int grow = rowBase + r;
            float4 v = make_float4(0.f, 0.f, 0.f, 0.f);
            if (grow < N_NODES)
                v = *(const float4*)&g_B[(size_t)grow * KDIM + kb + q * 4];
            As[r][q * 4]     = tf32cvt(v.x);
            As[r][q * 4 + 1] = tf32cvt(v.y);
            As[r][q * 4 + 2] = tf32cvt(v.z);
            As[r][q * 4 + 3] = tf32cvt(v.w);
        }
        #pragma unroll
        for (int it = 0; it < 4; it++) {
            int f = tid + 128 * it;
            int k = f >> 4, q = f & 15;
            float4 v = *(const float4*)&W[(kb + k) * HID + q * 4];
            Bs[k][q * 4]     = tf32cvt(v.x);
            Bs[k][q * 4 + 1] = tf32cvt(v.y);
            Bs[k][q * 4 + 2] = tf32cvt(v.z);
            Bs[k][q * 4 + 3] = tf32cvt(v.w);
        }
        __syncthreads();
        #pragma unroll
        for (int kk = 0; kk < 4; kk++) {
            unsigned a0 = As[wrow + g][kk * 8 + tig];
            unsigned a1 = As[wrow + g + 8][kk * 8 + tig];
            unsigned a2 = As[wrow + g][kk * 8 + tig + 4];
            unsigned a3 = As[wrow + g + 8][kk * 8 + tig + 4];
            #pragma unroll
            for (int nt = 0; nt < 8; nt++) {
                unsigned b0 = Bs[kk * 8 + tig][nt * 8 + g];
                unsigned b1 = Bs[kk * 8 + tig + 4][nt * 8 + g];
                mma_tf32(acc[nt], a0, a1, a2, a3, b0, b1);
            }
        }
        __syncthreads();
    }

    int r0 = rowBase + wrow + g;
    int r1 = r0 + 8;
    float cS[8][2], cQ[8][2];
    #pragma unroll
    for (int nt = 0; nt < 8; nt++) {
        float v0 = fmaxf(acc[nt][0], 0.f);
        float v1 = fmaxf(acc[nt][1], 0.f);
        float v2 = fmaxf(acc[nt][2], 0.f);
        float v3 = fmaxf(acc[nt][3], 0.f);
        int col = nt * 8 + tig * 2;
        if (r0 < N_NODES) *(float2*)&g_R[r0 * HID + col] = make_float2(v0, v1);
        if (r1 < N_NODES) *(float2*)&g_R[r1 * HID + col] = make_float2(v2, v3);
        cS[nt][0] = v0 + v2;  cQ[nt][0] = v0 * v0 + v2 * v2;
        cS[nt][1] = v1 + v3;  cQ[nt][1] = v1 * v1 + v3 * v3;
    }
    #pragma unroll
    for (int o = 16; o >= 4; o >>= 1) {
        #pragma unroll
        for (int nt = 0; nt < 8; nt++) {
            cS[nt][0] += __shfl_xor_sync(0xffffffffu, cS[nt][0], o);
            cS[nt][1] += __shfl_xor_sync(0xffffffffu, cS[nt][1], o);
            cQ[nt][0] += __shfl_xor_sync(0xffffffffu, cQ[nt][0], o);
            cQ[nt][1] += __shfl_xor_sync(0xffffffffu, cQ[nt][1], o);
        }
    }
    __syncthreads();
    float* smr = (float*)&As[0][0];
    if (g == 0) {
        #pragma unroll
        for (int nt = 0; nt < 8; nt++) {
            int col = nt * 8 + tig * 2;
            smr[w * HID + col]           = cS[nt][0];
            smr[w * HID + col + 1]       = cS[nt][1];
            smr[256 + w * HID + col]     = cQ[nt][0];
            smr[256 + w * HID + col + 1] = cQ[nt][1];
        }
    }
    __syncthreads();
    if (tid < HID) {
        float s = 0.f, s2 = 0.f;
        #pragma unroll
        for (int ww = 0; ww < 4; ww++) {
            s  += smr[ww * HID + tid];
            s2 += smr[256 + ww * HID + tid];
        }
        atomicAdd(&g_sums[tid], s);
        atomicAdd(&g_sumsq[tid], s2);
    }
}

// ------- BN normalize + shortcut + pooling + (last block) classifier -------
__global__ void k_norm_pool(const float* __restrict__ feat, int hinsel, int houtsel,
                            const float* __restrict__ gamma, const float* __restrict__ beta,
                            const int* __restrict__ gids, int shortcut,
                            const float* __restrict__ cW1, const float* __restrict__ cb1,
                            const float* __restrict__ cg1, const float* __restrict__ cbt1,
                            const float* __restrict__ cW2, const float* __restrict__ cb2,
                            float* __restrict__ out, int accumulate) {
    const float* __restrict__ hin = (hinsel == 0) ? feat : ((hinsel == 1) ? g_hA : g_hB);
    float* hout = (houtsel == 1) ? g_hA : g_hB;
    int tid = threadIdx.x;        // 512 -> 8 nodes x 64 cols per block
    int k = tid & 63, nl = tid >> 6;
    int n = blockIdx.x * 8 + nl;  // 3125*8 == 25000 exactly

    __shared__ float ps[N_GRAPHS * HID];
    for (int i = tid; i < N_GRAPHS * HID; i += 512) ps[i] = 0.f;
    __syncthreads();

    const float inv = 1.0f / (float)N_NODES;
    float mu = g_sums[k] * inv;
    float var = g_sumsq[k] * inv - mu * mu;
    float rstd = rsqrtf(var + 1e-5f);
    float v = gamma[k] * (g_R[n * HID + k] - mu) * rstd + beta[k];
    if (shortcut) v += hin[n * HID + k];
    hout[n * HID + k] = v;

    int g = gids[n];
    atomicAdd(&ps[g * HID + k], v);
    __syncthreads();

    int gmin = gids[blockIdx.x * 8];
    int gmax = gids[blockIdx.x * 8 + 7];
    int span = (gmax - gmin + 1) * HID;
    for (int i = tid; i < span; i += 512)
        atomicAdd(&g_pooled[gmin * HID + i], ps[gmin * HID + i]);

    // ---- last-block classifier ----
    __shared__ int s_last;
    __threadfence();
    __syncthreads();
    if (tid == 0) s_last = (atomicAdd(&g_done, 1) == (int)gridDim.x - 1) ? 1 : 0;
    __syncthreads();
    if (!s_last) return;

    __shared__ float xp[N_GRAPHS * HID];
    __shared__ float y[N_GRAPHS * 32];
    __shared__ float mus[32], rss[32];
    for (int i = tid; i < N_GRAPHS * HID; i += 512) xp[i] = g_pooled[i];
    __syncthreads();
    {
        int r = tid >> 5, c = tid & 31;
        float acc = cb1[c];
        #pragma unroll 8
        for (int j = 0; j < HID; j++) acc += xp[r * HID + j] * cW1[j * 32 + c];
        y[r * 32 + c] = acc;
    }
    __syncthreads();
    if (tid < 32) {
        float s = 0.f, s2 = 0.f;
        #pragma unroll
        for (int r = 0; r < N_GRAPHS; r++) {
            float vv = y[r * 32 + tid];
            s += vv; s2 += vv * vv;
        }
        float m = s / (float)N_GRAPHS;
        float vr = s2 / (float)N_GRAPHS - m * m;
        mus[tid] = m;
        rss[tid] = rsqrtf(vr + 1e-5f);
    }
    __syncthreads();
    {
        int r = tid >> 5, c = tid & 31;
        float vv = cg1[c] * (y[r * 32 + c] - mus[c]) * rss[c] + cbt1[c];
        y[r * 32 + c] = fmaxf(vv, 0.f);
    }
    __syncthreads();
    if (tid < N_GRAPHS * N_CLASSES) {
        int r = tid / N_CLASSES, c = tid % N_CLASSES;
        float acc = cb2[c];
        #pragma unroll
        for (int j = 0; j < 32; j++) acc += y[r * 32 + j] * cW2[j * N_CLASSES + c];
        if (accumulate) out[r * N_CLASSES + c] += acc;
        else            out[r * N_CLASSES + c] = acc;
    }
}

// ---------------- launcher -------------------------------------------------
extern "C" void kernel_launch(void* const* d_in, const int* in_sizes, int n_in,
                              void* d_out, int out_size) {
    const float* feature = (const float*)d_in[0];
    const float* spemb   = (const float*)d_in[1];
    const int*   src     = (const int*)d_in[2];
    const int*   dst     = (const int*)d_in[3];
    const int*   gids    = (const int*)d_in[4];
    const float* W[3]  = { (const float*)d_in[5], (const float*)d_in[6], (const float*)d_in[7] };
    const float* gm[3] = { (const float*)d_in[8], (const float*)d_in[10], (const float*)d_in[12] };
    const float* bt[3] = { (const float*)d_in[9], (const float*)d_in[11], (const float*)d_in[13] };
    const float* cW1  = (const float*)d_in[14];
    const float* cb1  = (const float*)d_in[15];
    const float* cg1  = (const float*)d_in[16];
    const float* cbt1 = (const float*)d_in[17];
    const float* cW2  = (const float*)d_in[18];
    const float* cb2  = (const float*)d_in[19];
    float* out = (float*)d_out;

    k_zero_cc<<<(N_NODES + 255) / 256, 256>>>();
    k_hist_dir<<<(N_EDGES + 255) / 256, 256>>>(src, dst, spemb);
    k_scan<<<1, 1024>>>();
    k_scatter<<<(N_EDGES + 255) / 256, 256>>>(src, dst);

    int hin = 0, hout = 1;
    for (int L = 0; L < 3; L++) {
        k_edge_agg<<<(N_NODES * 32 + 255) / 256, 256>>>(feature, hin);
        k_gemm_relu<<<(N_NODES + BM - 1) / BM, 128>>>(W[L]);
        k_norm_pool<<<N_NODES / 8, 512>>>(feature, hin, hout, gm[L], bt[L], gids,
                                          L > 0 ? 1 : 0,
                                          cW1, cb1, cg1, cbt1, cW2, cb2,
                                          out, L > 0 ? 1 : 0);
        hin = hout;
        hout = (hout == 1) ? 2 : 1;
    }
}

// round 6
// speedup vs baseline: 1.1404x; 1.1404x over previous
#include <cuda_runtime.h>
#include <cuda_bf16.h>
#include <math.h>

#define N_NODES 25000
#define N_EDGES 400000
#define HID 64
#define EMB 8
#define N_GRAPHS 16
#define N_CLASSES 10
#define KDIM 512   /* EMB*HID */
#define TM 16      /* node tile per block in fused layer kernel */
#define ASTRIDE 516  /* smem A row stride (mod 32 == 4 -> conflict-free frags) */

// ---------------- scratch (device globals; no allocation allowed) ----------
__device__ float g_hA[N_NODES * HID];
__device__ float g_hB[N_NODES * HID];
__device__ float g_R[N_NODES * HID];              // relu(agg)
__device__ float g_D[(size_t)N_EDGES * EMB];      // directions in ORIGINAL edge order
__device__ int2  g_se[N_EDGES];                   // CSR-ordered {src, edge_id}
__device__ int   g_rowptr[N_NODES + 1];
__device__ int   g_cnt[N_NODES];
__device__ int   g_cur[N_NODES];
__device__ float g_sums[HID];
__device__ float g_sumsq[HID];
__device__ float g_pooled[N_GRAPHS * HID];
__device__ int   g_done;

// ---------------- tf32 helpers ---------------------------------------------
__device__ __forceinline__ unsigned tf32cvt(float x) {
    unsigned r;
    asm("cvt.rna.tf32.f32 %0, %1;" : "=r"(r) : "f"(x));
    return r;
}
__device__ __forceinline__ void mma_tf32(float* c,
                                         unsigned a0, unsigned a1, unsigned a2, unsigned a3,
                                         unsigned b0, unsigned b1) {
    asm volatile(
        "mma.sync.aligned.m16n8k8.row.col.f32.tf32.tf32.f32 "
        "{%0,%1,%2,%3}, {%4,%5,%6,%7}, {%8,%9}, {%0,%1,%2,%3};"
        : "+f"(c[0]), "+f"(c[1]), "+f"(c[2]), "+f"(c[3])
        : "r"(a0), "r"(a1), "r"(a2), "r"(a3), "r"(b0), "r"(b1));
}

// ---------------- CSR build ------------------------------------------------
__global__ void k_zero_cc() {
    int i = blockIdx.x * blockDim.x + threadIdx.x;
    if (i < N_NODES) { g_cnt[i] = 0; g_cur[i] = 0; }
    if (blockIdx.x == 0) {
        int t = threadIdx.x;
        if (t < HID) { g_sums[t] = 0.f; g_sumsq[t] = 0.f; }
        if (t == 0) g_done = 0;
        for (int j = t; j < N_GRAPHS * HID; j += blockDim.x) g_pooled[j] = 0.f;
    }
}

// histogram of dst + per-edge normalized direction (coalesced write, edge order)
__global__ void k_hist_dir(const int* __restrict__ src, const int* __restrict__ dst,
                           const float* __restrict__ c) {
    int e = blockIdx.x * blockDim.x + threadIdx.x;
    if (e >= N_EDGES) return;
    int s = src[e], t = dst[e];
    atomicAdd(&g_cnt[t], 1);
    float4 s0 = __ldg((const float4*)&c[s * EMB]);
    float4 s1 = __ldg((const float4*)&c[s * EMB + 4]);
    float4 t0 = __ldg((const float4*)&c[t * EMB]);
    float4 t1 = __ldg((const float4*)&c[t * EMB + 4]);
    float4 d0 = make_float4(s0.x - t0.x, s0.y - t0.y, s0.z - t0.z, s0.w - t0.w);
    float4 d1 = make_float4(s1.x - t1.x, s1.y - t1.y, s1.z - t1.z, s1.w - t1.w);
    float nn = d0.x * d0.x + d0.y * d0.y + d0.z * d0.z + d0.w * d0.w
             + d1.x * d1.x + d1.y * d1.y + d1.z * d1.z + d1.w * d1.w;
    float sc = 1.0f / fmaxf(sqrtf(nn), 1e-12f);
    d0.x *= sc; d0.y *= sc; d0.z *= sc; d0.w *= sc;
    d1.x *= sc; d1.y *= sc; d1.z *= sc; d1.w *= sc;
    *(float4*)&g_D[(size_t)e * EMB]     = d0;
    *(float4*)&g_D[(size_t)e * EMB + 4] = d1;
}

// single-block scan: 1024 threads x 25 contiguous counts each
__global__ void k_scan() {
    const int PER = 25;
    __shared__ int wsum[32];
    int tid = threadIdx.x, lane = tid & 31, wid = tid >> 5;
    int base = tid * PER;
    int v[PER];
    int s = 0;
    #pragma unroll
    for (int j = 0; j < PER; j++) {
        int i = base + j;
        int cv = (i < N_NODES) ? g_cnt[i] : 0;
        v[j] = s;
        s += cv;
    }
    int x = s;
    #pragma unroll
    for (int o = 1; o < 32; o <<= 1) {
        int t = __shfl_up_sync(0xffffffffu, x, o);
        if (lane >= o) x += t;
    }
    if (lane == 31) wsum[wid] = x;
    __syncthreads();
    if (wid == 0) {
        int w = wsum[lane];
        #pragma unroll
        for (int o = 1; o < 32; o <<= 1) {
            int t = __shfl_up_sync(0xffffffffu, w, o);
            if (lane >= o) w += t;
        }
        wsum[lane] = w;
    }
    __syncthreads();
    int off = x - s + (wid > 0 ? wsum[wid - 1] : 0);
    #pragma unroll
    for (int j = 0; j < PER; j++) {
        int i = base + j;
        if (i <= N_NODES) g_rowptr[i] = off + v[j];
    }
}

// scatter edge -> CSR slot; only 8 bytes scattered per edge
__global__ void k_scatter(const int* __restrict__ src, const int* __restrict__ dst) {
    int e = blockIdx.x * blockDim.x + threadIdx.x;
    if (e >= N_EDGES) return;
    int s = src[e], t = dst[e];
    int p = g_rowptr[t] + atomicAdd(&g_cur[t], 1);
    g_se[p] = make_int2(s, e);
}

// ======== FUSED layer kernel: edge-agg (-> smem) + tf32 GEMM + BN stats =====
// Block: 256 threads (8 warps), 16-node tile.
// Phase 1: warp w aggregates nodes rowBase+2w, rowBase+2w+1 into registers,
//          stores tf32 rows to resident smem A[16][516].
// Phase 2: stream W in 32-k tiles; warp w computes output n-tile w (cols 8w..8w+7)
//          over all 16 rows; relu+store to g_R; column stats via shfl + atomics.
__global__ void k_layer(const float* __restrict__ feat, int hsel,
                        const float* __restrict__ W) {
    __shared__ unsigned As[TM * ASTRIDE];   // 33 KB
    __shared__ unsigned Ws[32][72];         // 9.2 KB
    const float* __restrict__ h = (hsel == 0) ? feat : ((hsel == 1) ? g_hA : g_hB);
    int tid = threadIdx.x;
    int lane = tid & 31, w = tid >> 5;
    int rowBase = blockIdx.x * TM;

    // ---- phase 1: aggregation ----
    #pragma unroll
    for (int q = 0; q < 2; q++) {
        int r = w * 2 + q;             // tile row
        int node = rowBase + r;
        float a0[EMB], a1[EMB];
        #pragma unroll
        for (int i = 0; i < EMB; i++) { a0[i] = 0.f; a1[i] = 0.f; }
        if (node < N_NODES) {
            int e0 = g_rowptr[node], e1 = g_rowptr[node + 1];
            #pragma unroll 2
            for (int e = e0; e < e1; e++) {
                int2 se = __ldg(&g_se[e]);
                float4 d0 = __ldg((const float4*)&g_D[(size_t)se.y * EMB]);
                float4 d1 = __ldg((const float4*)&g_D[(size_t)se.y * EMB + 4]);
                float h0 = __ldg(&h[se.x * HID + lane]);
                float h1 = __ldg(&h[se.x * HID + 32 + lane]);
                a0[0] += d0.x * h0;  a1[0] += d0.x * h1;
                a0[1] += d0.y * h0;  a1[1] += d0.y * h1;
                a0[2] += d0.z * h0;  a1[2] += d0.z * h1;
                a0[3] += d0.w * h0;  a1[3] += d0.w * h1;
                a0[4] += d1.x * h0;  a1[4] += d1.x * h1;
                a0[5] += d1.y * h0;  a1[5] += d1.y * h1;
                a0[6] += d1.z * h0;  a1[6] += d1.z * h1;
                a0[7] += d1.w * h0;  a1[7] += d1.w * h1;
            }
        }
        #pragma unroll
        for (int i = 0; i < EMB; i++) {
            As[r * ASTRIDE + i * HID + lane]      = tf32cvt(a0[i]);
            As[r * ASTRIDE + i * HID + 32 + lane] = tf32cvt(a1[i]);
        }
    }
    __syncthreads();

    // ---- phase 2: GEMM (16 x 64 x 512), warp w owns n-tile w ----
    int g = lane >> 2, tig = lane & 3;
    float acc[4] = {0.f, 0.f, 0.f, 0.f};
    for (int kb = 0; kb < KDIM; kb += 32) {
        #pragma unroll
        for (int it = 0; it < 2; it++) {
            int f = tid + 256 * it;        // 512 float4 loads of W tile
            int k = f >> 4, q = f & 15;
            float4 v = *(const float4*)&W[(kb + k) * HID + q * 4];
            Ws[k][q * 4]     = tf32cvt(v.x);
            Ws[k][q * 4 + 1] = tf32cvt(v.y);
            Ws[k][q * 4 + 2] = tf32cvt(v.z);
            Ws[k][q * 4 + 3] = tf32cvt(v.w);
        }
        __syncthreads();
        #pragma unroll
        for (int kk = 0; kk < 4; kk++) {
            int kc = kb + kk * 8;
            unsigned a0 = As[g * ASTRIDE + kc + tig];
            unsigned a1 = As[(g + 8) * ASTRIDE + kc + tig];
            unsigned a2 = As[g * ASTRIDE + kc + tig + 4];
            unsigned a3 = As[(g + 8) * ASTRIDE + kc + tig + 4];
            unsigned b0 = Ws[kk * 8 + tig][w * 8 + g];
            unsigned b1 = Ws[kk * 8 + tig + 4][w * 8 + g];
            mma_tf32(acc, a0, a1, a2, a3, b0, b1);
        }
        __syncthreads();
    }

    // ---- epilogue: relu + store + column stats ----
    int r0 = rowBase + g, r1 = r0 + 8;
    int col = w * 8 + tig * 2;
    float v0 = fmaxf(acc[0], 0.f), v1 = fmaxf(acc[1], 0.f);
    float v2 = fmaxf(acc[2], 0.f), v3 = fmaxf(acc[3], 0.f);
    if (r0 < N_NODES) *(float2*)&g_R[r0 * HID + col] = make_float2(v0, v1);
    if (r1 < N_NODES) *(float2*)&g_R[r1 * HID + col] = make_float2(v2, v3);
    float cS0 = v0 + v2, cS1 = v1 + v3;
    float cQ0 = v0 * v0 + v2 * v2, cQ1 = v1 * v1 + v3 * v3;
    #pragma unroll
    for (int o = 16; o >= 4; o >>= 1) {
        cS0 += __shfl_xor_sync(0xffffffffu, cS0, o);
        cS1 += __shfl_xor_sync(0xffffffffu, cS1, o);
        cQ0 += __shfl_xor_sync(0xffffffffu, cQ0, o);
        cQ1 += __shfl_xor_sync(0xffffffffu, cQ1, o);
    }
    if (g == 0) {
        atomicAdd(&g_sums[col], cS0);
        atomicAdd(&g_sums[col + 1], cS1);
        atomicAdd(&g_sumsq[col], cQ0);
        atomicAdd(&g_sumsq[col + 1], cQ1);
    }
}

// ------- BN normalize + shortcut + pooling + (last block) classifier -------
// Last block also re-zeros g_sums/g_sumsq/g_pooled/g_done for the next layer.
__global__ void k_norm_pool(const float* __restrict__ feat, int hinsel, int houtsel,
                            const float* __restrict__ gamma, const float* __restrict__ beta,
                            const int* __restrict__ gids, int shortcut,
                            const float* __restrict__ cW1, const float* __restrict__ cb1,
                            const float* __restrict__ cg1, const float* __restrict__ cbt1,
                            const float* __restrict__ cW2, const float* __restrict__ cb2,
                            float* __restrict__ out, int accumulate) {
    const float* __restrict__ hin = (hinsel == 0) ? feat : ((hinsel == 1) ? g_hA : g_hB);
    float* hout = (houtsel == 1) ? g_hA : g_hB;
    int tid = threadIdx.x;        // 512 -> 8 nodes x 64 cols per block
    int k = tid & 63, nl = tid >> 6;
    int n = blockIdx.x * 8 + nl;  // 3125*8 == 25000 exactly

    __shared__ float ps[N_GRAPHS * HID];
    for (int i = tid; i < N_GRAPHS * HID; i += 512) ps[i] = 0.f;
    __syncthreads();

    const float inv = 1.0f / (float)N_NODES;
    float mu = g_sums[k] * inv;
    float var = g_sumsq[k] * inv - mu * mu;
    float rstd = rsqrtf(var + 1e-5f);
    float v = gamma[k] * (g_R[n * HID + k] - mu) * rstd + beta[k];
    if (shortcut) v += hin[n * HID + k];
    hout[n * HID + k] = v;

    int g = gids[n];
    atomicAdd(&ps[g * HID + k], v);
    __syncthreads();

    int gmin = gids[blockIdx.x * 8];
    int gmax = gids[blockIdx.x * 8 + 7];
    int span = (gmax - gmin + 1) * HID;
    for (int i = tid; i < span; i += 512)
        atomicAdd(&g_pooled[gmin * HID + i], ps[gmin * HID + i]);

    // ---- last-block classifier + state reset ----
    __shared__ int s_last;
    __threadfence();
    __syncthreads();
    if (tid == 0) s_last = (atomicAdd(&g_done, 1) == (int)gridDim.x - 1) ? 1 : 0;
    __syncthreads();
    if (!s_last) return;

    __shared__ float xp[N_GRAPHS * HID];
    __shared__ float y[N_GRAPHS * 32];
    __shared__ float mus[32], rss[32];
    for (int i = tid; i < N_GRAPHS * HID; i += 512) {
        xp[i] = g_pooled[i];
        g_pooled[i] = 0.f;                 // reset for next layer
    }
    if (tid < HID) { g_sums[tid] = 0.f; g_sumsq[tid] = 0.f; }
    if (tid == 0) g_done = 0;
    __syncthreads();
    {
        int r = tid >> 5, c = tid & 31;
        float acc = cb1[c];
        #pragma unroll 8
        for (int j = 0; j < HID; j++) acc += xp[r * HID + j] * cW1[j * 32 + c];
        y[r * 32 + c] = acc;
    }
    __syncthreads();
    if (tid < 32) {
        float s = 0.f, s2 = 0.f;
        #pragma unroll
        for (int r = 0; r < N_GRAPHS; r++) {
            float vv = y[r * 32 + tid];
            s += vv; s2 += vv * vv;
        }
        float m = s / (float)N_GRAPHS;
        float vr = s2 / (float)N_GRAPHS - m * m;
        mus[tid] = m;
        rss[tid] = rsqrtf(vr + 1e-5f);
    }
    __syncthreads();
    {
        int r = tid >> 5, c = tid & 31;
        float vv = cg1[c] * (y[r * 32 + c] - mus[c]) * rss[c] + cbt1[c];
        y[r * 32 + c] = fmaxf(vv, 0.f);
    }
    __syncthreads();
    if (tid < N_GRAPHS * N_CLASSES) {
        int r = tid / N_CLASSES, c = tid % N_CLASSES;
        float acc = cb2[c];
        #pragma unroll
        for (int j = 0; j < 32; j++) acc += y[r * 32 + j] * cW2[j * N_CLASSES + c];
        if (accumulate) out[r * N_CLASSES + c] += acc;
        else            out[r * N_CLASSES + c] = acc;
    }
}

// ---------------- launcher -------------------------------------------------
extern "C" void kernel_launch(void* const* d_in, const int* in_sizes, int n_in,
                              void* d_out, int out_size) {
    const float* feature = (const float*)d_in[0];
    const float* spemb   = (const float*)d_in[1];
    const int*   src     = (const int*)d_in[2];
    const int*   dst     = (const int*)d_in[3];
    const int*   gids    = (const int*)d_in[4];
    const float* W[3]  = { (const float*)d_in[5], (const float*)d_in[6], (const float*)d_in[7] };
    const float* gm[3] = { (const float*)d_in[8], (const float*)d_in[10], (const float*)d_in[12] };
    const float* bt[3] = { (const float*)d_in[9], (const float*)d_in[11], (const float*)d_in[13] };
    const float* cW1  = (const float*)d_in[14];
    const float* cb1  = (const float*)d_in[15];
    const float* cg1  = (const float*)d_in[16];
    const float* cbt1 = (const float*)d_in[17];
    const float* cW2  = (const float*)d_in[18];
    const float* cb2  = (const float*)d_in[19];
    float* out = (float*)d_out;

    k_zero_cc<<<(N_NODES + 255) / 256, 256>>>();
    k_hist_dir<<<(N_EDGES + 255) / 256, 256>>>(src, dst, spemb);
    k_scan<<<1, 1024>>>();
    k_scatter<<<(N_EDGES + 255) / 256, 256>>>(src, dst);

    int hin = 0, hout = 1;
    for (int L = 0; L < 3; L++) {
        k_layer<<<(N_NODES + TM - 1) / TM, 256>>>(feature, hin, W[L]);
        k_norm_pool<<<N_NODES / 8, 512>>>(feature, hin, hout, gm[L], bt[L], gids,
                                          L > 0 ? 1 : 0,
                                          cW1, cb1, cg1, cbt1, cW2, cb2,
                                          out, L > 0 ? 1 : 0);
        hin = hout;
        hout = (hout == 1) ? 2 : 1;
    }
}

// round 7
// speedup vs baseline: 1.2487x; 1.0950x over previous
#include <cuda_runtime.h>
#include <cuda_bf16.h>
#include <math.h>

#define N_NODES 25000
#define N_EDGES 400000
#define HID 64
#define EMB 8
#define N_GRAPHS 16
#define N_CLASSES 10
#define KDIM 512     /* EMB*HID */
#define TM 32        /* node tile per block in fused layer kernel */
#define ASTRIDE 516  /* smem A row stride (mod 32 == 4 -> conflict-free frags) */
#define WSTRIDE 72   /* smem W row stride (mod 32 == 8 -> conflict-free frags) */
#define LAYER_THREADS 512
#define LAYER_SMEM ((TM * ASTRIDE + 32 * WSTRIDE) * 4)

// ---------------- scratch (device globals; no allocation allowed) ----------
__device__ float g_hA[N_NODES * HID];
__device__ float g_hB[N_NODES * HID];
__device__ float g_R[N_NODES * HID];              // relu(agg)
__device__ float g_D[(size_t)N_EDGES * EMB];      // directions in ORIGINAL edge order
__device__ int2  g_se[N_EDGES];                   // CSR-ordered {src, edge_id}
__device__ int   g_rowptr[N_NODES + 1];
__device__ int   g_cnt[N_NODES];
__device__ int   g_cur[N_NODES];
__device__ float g_sums[HID];
__device__ float g_sumsq[HID];
__device__ float g_pooled[N_GRAPHS * HID];
__device__ int   g_done;

// ---------------- tf32 helpers ---------------------------------------------
__device__ __forceinline__ unsigned tf32cvt(float x) {
    unsigned r;
    asm("cvt.rna.tf32.f32 %0, %1;" : "=r"(r) : "f"(x));
    return r;
}
__device__ __forceinline__ void mma_tf32(float* c,
                                         unsigned a0, unsigned a1, unsigned a2, unsigned a3,
                                         unsigned b0, unsigned b1) {
    asm volatile(
        "mma.sync.aligned.m16n8k8.row.col.f32.tf32.tf32.f32 "
        "{%0,%1,%2,%3}, {%4,%5,%6,%7}, {%8,%9}, {%0,%1,%2,%3};"
        : "+f"(c[0]), "+f"(c[1]), "+f"(c[2]), "+f"(c[3])
        : "r"(a0), "r"(a1), "r"(a2), "r"(a3), "r"(b0), "r"(b1));
}

// ---------------- CSR build ------------------------------------------------
__global__ void k_zero_cc() {
    int i = blockIdx.x * blockDim.x + threadIdx.x;
    if (i < N_NODES) { g_cnt[i] = 0; g_cur[i] = 0; }
    if (blockIdx.x == 0) {
        int t = threadIdx.x;
        if (t < HID) { g_sums[t] = 0.f; g_sumsq[t] = 0.f; }
        if (t == 0) g_done = 0;
        for (int j = t; j < N_GRAPHS * HID; j += blockDim.x) g_pooled[j] = 0.f;
    }
}

// histogram of dst + per-edge normalized direction (coalesced write, edge order)
__global__ void k_hist_dir(const int* __restrict__ src, const int* __restrict__ dst,
                           const float* __restrict__ c) {
    int e = blockIdx.x * blockDim.x + threadIdx.x;
    if (e >= N_EDGES) return;
    int s = src[e], t = dst[e];
    atomicAdd(&g_cnt[t], 1);
    float4 s0 = __ldg((const float4*)&c[s * EMB]);
    float4 s1 = __ldg((const float4*)&c[s * EMB + 4]);
    float4 t0 = __ldg((const float4*)&c[t * EMB]);
    float4 t1 = __ldg((const float4*)&c[t * EMB + 4]);
    float4 d0 = make_float4(s0.x - t0.x, s0.y - t0.y, s0.z - t0.z, s0.w - t0.w);
    float4 d1 = make_float4(s1.x - t1.x, s1.y - t1.y, s1.z - t1.z, s1.w - t1.w);
    float nn = d0.x * d0.x + d0.y * d0.y + d0.z * d0.z + d0.w * d0.w
             + d1.x * d1.x + d1.y * d1.y + d1.z * d1.z + d1.w * d1.w;
    float sc = 1.0f / fmaxf(sqrtf(nn), 1e-12f);
    d0.x *= sc; d0.y *= sc; d0.z *= sc; d0.w *= sc;
    d1.x *= sc; d1.y *= sc; d1.z *= sc; d1.w *= sc;
    *(float4*)&g_D[(size_t)e * EMB]     = d0;
    *(float4*)&g_D[(size_t)e * EMB + 4] = d1;
}

// single-block scan: 1024 threads x 25 contiguous counts each
__global__ void k_scan() {
    const int PER = 25;
    __shared__ int wsum[32];
    int tid = threadIdx.x, lane = tid & 31, wid = tid >> 5;
    int base = tid * PER;
    int v[PER];
    int s = 0;
    #pragma unroll
    for (int j = 0; j < PER; j++) {
        int i = base + j;
        int cv = (i < N_NODES) ? g_cnt[i] : 0;
        v[j] = s;
        s += cv;
    }
    int x = s;
    #pragma unroll
    for (int o = 1; o < 32; o <<= 1) {
        int t = __shfl_up_sync(0xffffffffu, x, o);
        if (lane >= o) x += t;
    }
    if (lane == 31) wsum[wid] = x;
    __syncthreads();
    if (wid == 0) {
        int w = wsum[lane];
        #pragma unroll
        for (int o = 1; o < 32; o <<= 1) {
            int t = __shfl_up_sync(0xffffffffu, w, o);
            if (lane >= o) w += t;
        }
        wsum[lane] = w;
    }
    __syncthreads();
    int off = x - s + (wid > 0 ? wsum[wid - 1] : 0);
    #pragma unroll
    for (int j = 0; j < PER; j++) {
        int i = base + j;
        if (i <= N_NODES) g_rowptr[i] = off + v[j];
    }
}

// scatter edge -> CSR slot; only 8 bytes scattered per edge
__global__ void k_scatter(const int* __restrict__ src, const int* __restrict__ dst) {
    int e = blockIdx.x * blockDim.x + threadIdx.x;
    if (e >= N_EDGES) return;
    int s = src[e], t = dst[e];
    int p = g_rowptr[t] + atomicAdd(&g_cur[t], 1);
    g_se[p] = make_int2(s, e);
}

// ======== FUSED layer kernel: edge-agg (-> smem) + tf32 GEMM + BN stats =====
// Block: 512 threads (16 warps), 32-node tile.
// Phase 1: warp w aggregates nodes rowBase+2w, rowBase+2w+1 -> tf32 smem A rows.
// Phase 2: stream W in 32-k tiles; warp w = (rg = w>>3, wn = w&7) computes
//          rows rg*16..rg*16+15 x cols wn*8..wn*8+7; relu+store; stats atomics.
__global__ void __launch_bounds__(LAYER_THREADS)
k_layer(const float* __restrict__ feat, int hsel, const float* __restrict__ W) {
    extern __shared__ unsigned smem_u[];
    unsigned* As = smem_u;                    // TM * ASTRIDE
    unsigned* Ws = smem_u + TM * ASTRIDE;     // 32 * WSTRIDE
    const float* __restrict__ h = (hsel == 0) ? feat : ((hsel == 1) ? g_hA : g_hB);
    int tid = threadIdx.x;
    int lane = tid & 31, w = tid >> 5;
    int rowBase = blockIdx.x * TM;

    // ---- phase 1: aggregation (warp w -> tile rows 2w, 2w+1) ----
    #pragma unroll
    for (int q = 0; q < 2; q++) {
        int r = w * 2 + q;
        int node = rowBase + r;
        float a0[EMB], a1[EMB];
        #pragma unroll
        for (int i = 0; i < EMB; i++) { a0[i] = 0.f; a1[i] = 0.f; }
        if (node < N_NODES) {
            int e0 = g_rowptr[node], e1 = g_rowptr[node + 1];
            #pragma unroll 2
            for (int e = e0; e < e1; e++) {
                int2 se = __ldg(&g_se[e]);
                float4 d0 = __ldg((const float4*)&g_D[(size_t)se.y * EMB]);
                float4 d1 = __ldg((const float4*)&g_D[(size_t)se.y * EMB + 4]);
                float h0 = __ldg(&h[se.x * HID + lane]);
                float h1 = __ldg(&h[se.x * HID + 32 + lane]);
                a0[0] += d0.x * h0;  a1[0] += d0.x * h1;
                a0[1] += d0.y * h0;  a1[1] += d0.y * h1;
                a0[2] += d0.z * h0;  a1[2] += d0.z * h1;
                a0[3] += d0.w * h0;  a1[3] += d0.w * h1;
                a0[4] += d1.x * h0;  a1[4] += d1.x * h1;
                a0[5] += d1.y * h0;  a1[5] += d1.y * h1;
                a0[6] += d1.z * h0;  a1[6] += d1.z * h1;
                a0[7] += d1.w * h0;  a1[7] += d1.w * h1;
            }
        }
        #pragma unroll
        for (int i = 0; i < EMB; i++) {
            As[r * ASTRIDE + i * HID + lane]      = tf32cvt(a0[i]);
            As[r * ASTRIDE + i * HID + 32 + lane] = tf32cvt(a1[i]);
        }
    }
    __syncthreads();

    // ---- phase 2: GEMM (32 x 64 x 512) ----
    int g = lane >> 2, tig = lane & 3;
    int rg = w >> 3, wn = w & 7;
    int arow0 = (rg * 16 + g) * ASTRIDE;
    int arow1 = (rg * 16 + g + 8) * ASTRIDE;
    float acc[4] = {0.f, 0.f, 0.f, 0.f};
    for (int kb = 0; kb < KDIM; kb += 32) {
        {
            int k = tid >> 4, q = tid & 15;    // 512 threads -> 512 float4 of W tile
            float4 v = *(const float4*)&W[(kb + k) * HID + q * 4];
            Ws[k * WSTRIDE + q * 4]     = tf32cvt(v.x);
            Ws[k * WSTRIDE + q * 4 + 1] = tf32cvt(v.y);
            Ws[k * WSTRIDE + q * 4 + 2] = tf32cvt(v.z);
            Ws[k * WSTRIDE + q * 4 + 3] = tf32cvt(v.w);
        }
        __syncthreads();
        #pragma unroll
        for (int kk = 0; kk < 4; kk++) {
            int kc = kb + kk * 8;
            unsigned a0 = As[arow0 + kc + tig];
            unsigned a1 = As[arow1 + kc + tig];
            unsigned a2 = As[arow0 + kc + tig + 4];
            unsigned a3 = As[arow1 + kc + tig + 4];
            unsigned b0 = Ws[(kk * 8 + tig) * WSTRIDE + wn * 8 + g];
            unsigned b1 = Ws[(kk * 8 + tig + 4) * WSTRIDE + wn * 8 + g];
            mma_tf32(acc, a0, a1, a2, a3, b0, b1);
        }
        __syncthreads();
    }

    // ---- epilogue: relu + store + column stats ----
    int r0 = rowBase + rg * 16 + g, r1 = r0 + 8;
    int col = wn * 8 + tig * 2;
    float v0 = fmaxf(acc[0], 0.f), v1 = fmaxf(acc[1], 0.f);
    float v2 = fmaxf(acc[2], 0.f), v3 = fmaxf(acc[3], 0.f);
    if (r0 < N_NODES) *(float2*)&g_R[r0 * HID + col] = make_float2(v0, v1);
    if (r1 < N_NODES) *(float2*)&g_R[r1 * HID + col] = make_float2(v2, v3);
    float cS0 = v0 + v2, cS1 = v1 + v3;
    float cQ0 = v0 * v0 + v2 * v2, cQ1 = v1 * v1 + v3 * v3;
    #pragma unroll
    for (int o = 16; o >= 4; o >>= 1) {
        cS0 += __shfl_xor_sync(0xffffffffu, cS0, o);
        cS1 += __shfl_xor_sync(0xffffffffu, cS1, o);
        cQ0 += __shfl_xor_sync(0xffffffffu, cQ0, o);
        cQ1 += __shfl_xor_sync(0xffffffffu, cQ1, o);
    }
    if (g == 0) {
        atomicAdd(&g_sums[col], cS0);
        atomicAdd(&g_sums[col + 1], cS1);
        atomicAdd(&g_sumsq[col], cQ0);
        atomicAdd(&g_sumsq[col + 1], cQ1);
    }
}

// ------- BN normalize + shortcut + pooling + (last block) classifier -------
// Last block also re-zeros g_sums/g_sumsq/g_pooled/g_done for the next layer.
__global__ void k_norm_pool(const float* __restrict__ feat, int hinsel, int houtsel,
                            const float* __restrict__ gamma, const float* __restrict__ beta,
                            const int* __restrict__ gids, int shortcut,
                            const float* __restrict__ cW1, const float* __restrict__ cb1,
                            const float* __restrict__ cg1, const float* __restrict__ cbt1,
                            const float* __restrict__ cW2, const float* __restrict__ cb2,
                            float* __restrict__ out, int accumulate) {
    const float* __restrict__ hin = (hinsel == 0) ? feat : ((hinsel == 1) ? g_hA : g_hB);
    float* hout = (houtsel == 1) ? g_hA : g_hB;
    int tid = threadIdx.x;        // 512 -> 8 nodes x 64 cols per block
    int k = tid & 63, nl = tid >> 6;
    int n = blockIdx.x * 8 + nl;  // 3125*8 == 25000 exactly

    __shared__ float ps[N_GRAPHS * HID];
    for (int i = tid; i < N_GRAPHS * HID; i += 512) ps[i] = 0.f;
    __syncthreads();

    const float inv = 1.0f / (float)N_NODES;
    float mu = g_sums[k] * inv;
    float var = g_sumsq[k] * inv - mu * mu;
    float rstd = rsqrtf(var + 1e-5f);
    float v = gamma[k] * (g_R[n * HID + k] - mu) * rstd + beta[k];
    if (shortcut) v += hin[n * HID + k];
    hout[n * HID + k] = v;

    int g = gids[n];
    atomicAdd(&ps[g * HID + k], v);
    __syncthreads();

    int gmin = gids[blockIdx.x * 8];
    int gmax = gids[blockIdx.x * 8 + 7];
    int span = (gmax - gmin + 1) * HID;
    for (int i = tid; i < span; i += 512)
        atomicAdd(&g_pooled[gmin * HID + i], ps[gmin * HID + i]);

    // ---- last-block classifier + state reset ----
    __shared__ int s_last;
    __threadfence();
    __syncthreads();
    if (tid == 0) s_last = (atomicAdd(&g_done, 1) == (int)gridDim.x - 1) ? 1 : 0;
    __syncthreads();
    if (!s_last) return;

    __shared__ float xp[N_GRAPHS * HID];
    __shared__ float y[N_GRAPHS * 32];
    __shared__ float mus[32], rss[32];
    for (int i = tid; i < N_GRAPHS * HID; i += 512) {
        xp[i] = g_pooled[i];
        g_pooled[i] = 0.f;                 // reset for next layer
    }
    if (tid < HID) { g_sums[tid] = 0.f; g_sumsq[tid] = 0.f; }
    if (tid == 0) g_done = 0;
    __syncthreads();
    {
        int r = tid >> 5, c = tid & 31;
        float acc = cb1[c];
        #pragma unroll 8
        for (int j = 0; j < HID; j++) acc += xp[r * HID + j] * cW1[j * 32 + c];
        y[r * 32 + c] = acc;
    }
    __syncthreads();
    if (tid < 32) {
        float s = 0.f, s2 = 0.f;
        #pragma unroll
        for (int r = 0; r < N_GRAPHS; r++) {
            float vv = y[r * 32 + tid];
            s += vv; s2 += vv * vv;
        }
        float m = s / (float)N_GRAPHS;
        float vr = s2 / (float)N_GRAPHS - m * m;
        mus[tid] = m;
        rss[tid] = rsqrtf(vr + 1e-5f);
    }
    __syncthreads();
    {
        int r = tid >> 5, c = tid & 31;
        float vv = cg1[c] * (y[r * 32 + c] - mus[c]) * rss[c] + cbt1[c];
        y[r * 32 + c] = fmaxf(vv, 0.f);
    }
    __syncthreads();
    if (tid < N_GRAPHS * N_CLASSES) {
        int r = tid / N_CLASSES, c = tid % N_CLASSES;
        float acc = cb2[c];
        #pragma unroll
        for (int j = 0; j < 32; j++) acc += y[r * 32 + j] * cW2[j * N_CLASSES + c];
        if (accumulate) out[r * N_CLASSES + c] += acc;
        else            out[r * N_CLASSES + c] = acc;
    }
}

// ---------------- launcher -------------------------------------------------
extern "C" void kernel_launch(void* const* d_in, const int* in_sizes, int n_in,
                              void* d_out, int out_size) {
    const float* feature = (const float*)d_in[0];
    const float* spemb   = (const float*)d_in[1];
    const int*   src     = (const int*)d_in[2];
    const int*   dst     = (const int*)d_in[3];
    const int*   gids    = (const int*)d_in[4];
    const float* W[3]  = { (const float*)d_in[5], (const float*)d_in[6], (const float*)d_in[7] };
    const float* gm[3] = { (const float*)d_in[8], (const float*)d_in[10], (const float*)d_in[12] };
    const float* bt[3] = { (const float*)d_in[9], (const float*)d_in[11], (const float*)d_in[13] };
    const float* cW1  = (const float*)d_in[14];
    const float* cb1  = (const float*)d_in[15];
    const float* cg1  = (const float*)d_in[16];
    const float* cbt1 = (const float*)d_in[17];
    const float* cW2  = (const float*)d_in[18];
    const float* cb2  = (const float*)d_in[19];
    float* out = (float*)d_out;

    static int smem_set = 0;
    if (!smem_set) {
        cudaFuncSetAttribute(k_layer, cudaFuncAttributeMaxDynamicSharedMemorySize,
                             LAYER_SMEM);
        smem_set = 1;
    }

    k_zero_cc<<<(N_NODES + 255) / 256, 256>>>();
    k_hist_dir<<<(N_EDGES + 255) / 256, 256>>>(src, dst, spemb);
    k_scan<<<1, 1024>>>();
    k_scatter<<<(N_EDGES + 255) / 256, 256>>>(src, dst);

    int hin = 0, hout = 1;
    for (int L = 0; L < 3; L++) {
        k_layer<<<(N_NODES + TM - 1) / TM, LAYER_THREADS, LAYER_SMEM>>>(feature, hin, W[L]);
        k_norm_pool<<<N_NODES / 8, 512>>>(feature, hin, hout, gm[L], bt[L], gids,
                                          L > 0 ? 1 : 0,
                                          cW1, cb1, cg1, cbt1, cW2, cb2,
                                          out, L > 0 ? 1 : 0);
        hin = hout;
        hout = (hout == 1) ? 2 : 1;
    }
}